// round 3
// baseline (speedup 1.0000x reference)
#include <cuda_runtime.h>

// N = 1024 rows, DIM = 256, HID = 512

__device__ float g_hid1[1024 * 512];
__device__ float g_hid2[1024 * 512];
__device__ float g_colstats[2][2][256];  // [matrix][0=sum,1=sumsq][col]
__device__ double g_acc;

// ---------------------------------------------------------------------------
// Column sums / sums-of-squares over the 1024 rows of a [1024,256] matrix.
// grid.x = 16: bit3 selects matrix, bits0-2 select 32-column group.
// Block 0 also zeroes the global accumulator (consumed only by later kernels).
// ---------------------------------------------------------------------------
__global__ void mi_stats(const float* __restrict__ P, const float* __restrict__ G) {
    if (blockIdx.x == 0 && threadIdx.x == 0 && threadIdx.y == 0) g_acc = 0.0;
    int m = blockIdx.x >> 3;
    int cg = blockIdx.x & 7;
    const float* Y = m ? G : P;
    int col = cg * 32 + threadIdx.x;
    float s = 0.f, q = 0.f;
    for (int r = threadIdx.y; r < 1024; r += 8) {
        float v = Y[r * 256 + col];
        s += v;
        q += v * v;
    }
    __shared__ float shs[8][32], shq[8][32];
    shs[threadIdx.y][threadIdx.x] = s;
    shq[threadIdx.y][threadIdx.x] = q;
    __syncthreads();
    if (threadIdx.y == 0) {
        float ts = 0.f, tq = 0.f;
#pragma unroll
        for (int j = 0; j < 8; j++) {
            ts += shs[j][threadIdx.x];
            tq += shq[j][threadIdx.x];
        }
        g_colstats[m][0][col] = ts;
        g_colstats[m][1][col] = tq;
    }
}

// ---------------------------------------------------------------------------
// Relu-GEMM body: C[1024,512] = relu(A @ B + bias), 64x64 tile, 4x4/thread,
// double-buffered smem with register prefetch (one __syncthreads per tile).
// CONCAT: logical A = [A | A2], each half row-stride 256 (requires K == 512).
// ---------------------------------------------------------------------------
template <int K, bool CONCAT>
__device__ __forceinline__ void relu_body(
    const float* __restrict__ A, const float* __restrict__ A2,
    const float* __restrict__ B, const float* __restrict__ bias,
    float* __restrict__ C,
    float (&As)[2][16][64], float (&Bs)[2][16][64]) {
    constexpr int NC = 512, BM = 64, BN = 64, BK = 16, T = K / BK;

    const int tid = threadIdx.x;  // 256
    const int tx = tid & 15;
    const int ty = tid >> 4;
    const int rowBase = blockIdx.y * BM;
    const int colBase = blockIdx.x * BN;

    const int la_row = tid >> 2;      // 0..63
    const int la_k = (tid & 3) * 4;   // 0,4,8,12
    const int lb_row = tid >> 4;      // 0..15
    const int lb_c = (tid & 15) * 4;  // 0..60

    constexpr int ASTRIDE = CONCAT ? 256 : K;

    auto ldA = [&](int t) {
        int gk = t * BK + la_k;
        const float* Asrc = A;
        if (CONCAT && gk >= 256) { Asrc = A2; gk -= 256; }
        return *reinterpret_cast<const float4*>(
            Asrc + (size_t)(rowBase + la_row) * ASTRIDE + gk);
    };
    auto ldB = [&](int t) {
        return *reinterpret_cast<const float4*>(
            B + (size_t)(t * BK + lb_row) * NC + colBase + lb_c);
    };
    auto stTile = [&](int buf, float4 a4, float4 b4) {
        As[buf][la_k + 0][la_row] = a4.x;
        As[buf][la_k + 1][la_row] = a4.y;
        As[buf][la_k + 2][la_row] = a4.z;
        As[buf][la_k + 3][la_row] = a4.w;
        *reinterpret_cast<float4*>(&Bs[buf][lb_row][lb_c]) = b4;
    };

    float acc[4][4] = {};

    stTile(0, ldA(0), ldB(0));
    __syncthreads();

    for (int t = 0; t < T; t++) {
        int cur = t & 1;
        float4 pa, pb;
        if (t + 1 < T) { pa = ldA(t + 1); pb = ldB(t + 1); }
#pragma unroll
        for (int k = 0; k < BK; k++) {
            float4 av = *reinterpret_cast<const float4*>(&As[cur][k][ty * 4]);
            float4 bv = *reinterpret_cast<const float4*>(&Bs[cur][k][tx * 4]);
            float a[4] = {av.x, av.y, av.z, av.w};
            float b[4] = {bv.x, bv.y, bv.z, bv.w};
#pragma unroll
            for (int i = 0; i < 4; i++)
#pragma unroll
                for (int j = 0; j < 4; j++)
                    acc[i][j] = fmaf(a[i], b[j], acc[i][j]);
        }
        if (t + 1 < T) stTile((t + 1) & 1, pa, pb);
        __syncthreads();
    }

#pragma unroll
    for (int i = 0; i < 4; i++) {
        int row = rowBase + ty * 4 + i;
        int col = colBase + tx * 4;
        float4 v;
        v.x = fmaxf(acc[i][0] + bias[col + 0], 0.f);
        v.y = fmaxf(acc[i][1] + bias[col + 1], 0.f);
        v.z = fmaxf(acc[i][2] + bias[col + 2], 0.f);
        v.w = fmaxf(acc[i][3] + bias[col + 3], 0.f);
        *reinterpret_cast<float4*>(C + (size_t)row * NC + col) = v;
    }
}

// Merged relu-GEMM launch: blockIdx.z = 0 -> branch 1 (K=256), 1 -> branch 2
// (K=512, concat [hist|path]). 256 CTAs total.
__global__ void __launch_bounds__(256)
mi_relu(const float* __restrict__ hist, const float* __restrict__ path,
        const float* __restrict__ W1, const float* __restrict__ b1,
        const float* __restrict__ W1g, const float* __restrict__ b1g,
        float* __restrict__ hid1, float* __restrict__ hid2) {
    __shared__ float As[2][16][64];
    __shared__ float Bs[2][16][64];
    if (blockIdx.z == 0)
        relu_body<256, false>(hist, nullptr, W1, b1, hid1, As, Bs);
    else
        relu_body<512, true>(hist, path, W1g, b1g, hid2, As, Bs);
}

// ---------------------------------------------------------------------------
// Merged CLUB GEMM: mu = A[1024,512] @ B[512,256] + bias, fused CLUB epilogue.
// 64x32 tile, 4x2 per thread, double-buffered. blockIdx.z selects branch.
// Per element: 0.5*(E[y^2]_d - 2*mu*ybar_d + mu^2) - 0.5*(mu - y_id)^2
// ---------------------------------------------------------------------------
__global__ void __launch_bounds__(256)
mi_club(const float* __restrict__ hid1, const float* __restrict__ W2,
        const float* __restrict__ b2, const float* __restrict__ path,
        const float* __restrict__ hid2, const float* __restrict__ W2g,
        const float* __restrict__ b2g, const float* __restrict__ glob) {
    constexpr int K = 512, NC = 256, BM = 64, BN = 32, BK = 16, T = K / BK;
    __shared__ float As[2][BK][BM];
    __shared__ float Bs[2][BK][BN];

    const int z = blockIdx.z;
    const float* __restrict__ A = z ? hid2 : hid1;
    const float* __restrict__ B = z ? W2g : W2;
    const float* __restrict__ bias = z ? b2g : b2;
    const float* __restrict__ Y = z ? glob : path;

    const int tid = threadIdx.x;  // 256
    const int tx = tid & 15;      // cols (2 each)
    const int ty = tid >> 4;      // rows (4 each)
    const int rowBase = blockIdx.y * BM;
    const int colBase = blockIdx.x * BN;

    const int la_row = tid >> 2;      // 0..63
    const int la_k = (tid & 3) * 4;   // 0,4,8,12
    const int lb_row = tid >> 4;      // 0..15
    const int lb_c = (tid & 15) * 2;  // 0..30

    auto ldA = [&](int t) {
        return *reinterpret_cast<const float4*>(
            A + (size_t)(rowBase + la_row) * K + t * BK + la_k);
    };
    auto ldB = [&](int t) {
        return *reinterpret_cast<const float2*>(
            B + (size_t)(t * BK + lb_row) * NC + colBase + lb_c);
    };
    auto stTile = [&](int buf, float4 a4, float2 b2v) {
        As[buf][la_k + 0][la_row] = a4.x;
        As[buf][la_k + 1][la_row] = a4.y;
        As[buf][la_k + 2][la_row] = a4.z;
        As[buf][la_k + 3][la_row] = a4.w;
        *reinterpret_cast<float2*>(&Bs[buf][lb_row][lb_c]) = b2v;
    };

    float acc[4][2] = {};

    stTile(0, ldA(0), ldB(0));
    __syncthreads();

    for (int t = 0; t < T; t++) {
        int cur = t & 1;
        float4 pa;
        float2 pb;
        if (t + 1 < T) { pa = ldA(t + 1); pb = ldB(t + 1); }
#pragma unroll
        for (int k = 0; k < BK; k++) {
            float4 av = *reinterpret_cast<const float4*>(&As[cur][k][ty * 4]);
            float2 bv = *reinterpret_cast<const float2*>(&Bs[cur][k][tx * 2]);
            float a[4] = {av.x, av.y, av.z, av.w};
            float b[2] = {bv.x, bv.y};
#pragma unroll
            for (int i = 0; i < 4; i++)
#pragma unroll
                for (int j = 0; j < 2; j++)
                    acc[i][j] = fmaf(a[i], b[j], acc[i][j]);
        }
        if (t + 1 < T) stTile((t + 1) & 1, pa, pb);
        __syncthreads();
    }

    float local = 0.f;
#pragma unroll
    for (int i = 0; i < 4; i++) {
        int row = rowBase + ty * 4 + i;
#pragma unroll
        for (int j = 0; j < 2; j++) {
            int col = colBase + tx * 2 + j;
            float mu = acc[i][j] + bias[col];
            float y = Y[(size_t)row * 256 + col];
            float ybar = g_colstats[z][0][col] * (1.f / 1024.f);
            float ey2 = g_colstats[z][1][col] * (1.f / 1024.f);
            float d = mu - y;
            local += 0.5f * (ey2 - 2.f * mu * ybar + mu * mu) - 0.5f * d * d;
        }
    }
    __shared__ float red[256];
    red[tid] = local;
    __syncthreads();
    for (int s = 128; s > 0; s >>= 1) {
        if (tid < s) red[tid] += red[tid + s];
        __syncthreads();
    }
    if (tid == 0) atomicAdd(&g_acc, (double)red[0]);
}

__global__ void mi_final(float* out) { out[0] = (float)(g_acc * (1.0 / 1024.0)); }

extern "C" void kernel_launch(void* const* d_in, const int* in_sizes, int n_in,
                              void* d_out, int out_size) {
    const float* hist = (const float*)d_in[0];
    const float* path = (const float*)d_in[1];
    const float* glob = (const float*)d_in[2];
    const float* W1 = (const float*)d_in[3];
    const float* b1 = (const float*)d_in[4];
    const float* W2 = (const float*)d_in[5];
    const float* b2 = (const float*)d_in[6];
    const float* W1g = (const float*)d_in[7];
    const float* b1g = (const float*)d_in[8];
    const float* W2g = (const float*)d_in[9];
    const float* b2g = (const float*)d_in[10];
    float* out = (float*)d_out;

    float *hid1 = nullptr, *hid2 = nullptr;
    cudaGetSymbolAddress((void**)&hid1, g_hid1);
    cudaGetSymbolAddress((void**)&hid2, g_hid2);

    mi_stats<<<16, dim3(32, 8)>>>(path, glob);
    mi_relu<<<dim3(8, 16, 2), 256>>>(hist, path, W1, b1, W1g, b1g, hid1, hid2);
    mi_club<<<dim3(8, 16, 2), 256>>>(hid1, W2, b2, path, hid2, W2g, b2g, glob);
    mi_final<<<1, 1>>>(out);
}

// round 6
// speedup vs baseline: 1.4742x; 1.4742x over previous
#include <cuda_runtime.h>

// N = 1024 rows, DIM = 256, HID = 512

__device__ float g_hid1[1024 * 512];
__device__ float g_hid2[1024 * 512];
__device__ float g_colstats[2][2][256];  // [matrix][0=sum,1=sumsq][col]
__device__ double g_acc;
__device__ unsigned int g_cnt;

// ---------------------------------------------------------------------------
// Stats block (runs inside mi_relu launch, blockIdx.x == 8):
// column sums / sums-of-squares over the 1024 rows of a [1024,256] matrix.
// blockIdx.z selects matrix, blockIdx.y selects 32-column group.
// Block (8,0,0) also zeroes the accumulator + completion counter.
// ---------------------------------------------------------------------------
__device__ void stats_block(const float* __restrict__ P, const float* __restrict__ G) {
    const int tid = threadIdx.x;         // 256 threads
    const int lx = tid & 31;             // column within group
    const int ly = tid >> 5;             // row phase 0..7
    if (blockIdx.y == 0 && blockIdx.z == 0 && tid == 0) {
        g_acc = 0.0;
        g_cnt = 0u;
    }
    const int m = blockIdx.z;
    const float* Y = m ? G : P;
    const int col = blockIdx.y * 32 + lx;
    float s = 0.f, q = 0.f;
    for (int r = ly; r < 1024; r += 8) {
        float v = Y[r * 256 + col];
        s += v;
        q += v * v;
    }
    __shared__ float shs[8][32], shq[8][32];
    shs[ly][lx] = s;
    shq[ly][lx] = q;
    __syncthreads();
    if (ly == 0) {
        float ts = 0.f, tq = 0.f;
#pragma unroll
        for (int j = 0; j < 8; j++) {
            ts += shs[j][lx];
            tq += shq[j][lx];
        }
        g_colstats[m][0][col] = ts;
        g_colstats[m][1][col] = tq;
    }
}

// ---------------------------------------------------------------------------
// Relu-GEMM body: C[1024,512] = relu(A @ B + bias).
// 128x64 tile, 8x4 per thread, double-buffered smem, register prefetch.
// As padded to stride 132 -> 2-way (not 4-way) transpose-store conflicts.
// CONCAT: logical A = [A | A2], each half row-stride 256 (requires K == 512).
// ---------------------------------------------------------------------------
template <int K, bool CONCAT>
__device__ __forceinline__ void relu_body(
    const float* __restrict__ A, const float* __restrict__ A2,
    const float* __restrict__ B, const float* __restrict__ bias,
    float* __restrict__ C,
    float (&As)[2][16][132], float (&Bs)[2][16][64]) {
    constexpr int NC = 512, BM = 128, BN = 64, BK = 16, T = K / BK;

    const int tid = threadIdx.x;  // 256
    const int tx = tid & 15;      // col group: 4 cols each
    const int ty = tid >> 4;      // row group: 8 rows each
    const int rowBase = blockIdx.y * BM;
    const int colBase = blockIdx.x * BN;

    // A loader: two float4 per thread; row = tid>>2 (+64), kq = (tid&3)*4
    // B loader: one float4 per thread; k = tid>>4, cq = (tid&15)*4
    const int a_row0 = tid >> 2;
    const int a_kq = (tid & 3) * 4;
    const int b_k = tid >> 4;
    const int b_c = (tid & 15) * 4;

    constexpr int ASTRIDE = CONCAT ? 256 : K;

    auto ldA = [&](int t, int row) {
        int gk = t * BK + a_kq;
        const float* Asrc = A;
        if (CONCAT && gk >= 256) { Asrc = A2; gk -= 256; }
        return *reinterpret_cast<const float4*>(
            Asrc + (size_t)(rowBase + row) * ASTRIDE + gk);
    };
    auto ldB = [&](int t) {
        return *reinterpret_cast<const float4*>(
            B + (size_t)(t * BK + b_k) * NC + colBase + b_c);
    };
    auto stTile = [&](int buf, float4 a0, float4 a1, float4 b4) {
        As[buf][a_kq + 0][a_row0] = a0.x;
        As[buf][a_kq + 1][a_row0] = a0.y;
        As[buf][a_kq + 2][a_row0] = a0.z;
        As[buf][a_kq + 3][a_row0] = a0.w;
        As[buf][a_kq + 0][a_row0 + 64] = a1.x;
        As[buf][a_kq + 1][a_row0 + 64] = a1.y;
        As[buf][a_kq + 2][a_row0 + 64] = a1.z;
        As[buf][a_kq + 3][a_row0 + 64] = a1.w;
        *reinterpret_cast<float4*>(&Bs[buf][b_k][b_c]) = b4;
    };

    float acc[8][4] = {};

    stTile(0, ldA(0, a_row0), ldA(0, a_row0 + 64), ldB(0));
    __syncthreads();

    for (int t = 0; t < T; t++) {
        int cur = t & 1;
        float4 pa0, pa1, pb;
        if (t + 1 < T) {
            pa0 = ldA(t + 1, a_row0);
            pa1 = ldA(t + 1, a_row0 + 64);
            pb = ldB(t + 1);
        }
#pragma unroll
        for (int k = 0; k < BK; k++) {
            float4 a0 = *reinterpret_cast<const float4*>(&As[cur][k][ty * 8]);
            float4 a1 = *reinterpret_cast<const float4*>(&As[cur][k][ty * 8 + 4]);
            float4 bv = *reinterpret_cast<const float4*>(&Bs[cur][k][tx * 4]);
            float a[8] = {a0.x, a0.y, a0.z, a0.w, a1.x, a1.y, a1.z, a1.w};
            float b[4] = {bv.x, bv.y, bv.z, bv.w};
#pragma unroll
            for (int i = 0; i < 8; i++)
#pragma unroll
                for (int j = 0; j < 4; j++)
                    acc[i][j] = fmaf(a[i], b[j], acc[i][j]);
        }
        if (t + 1 < T) stTile((t + 1) & 1, pa0, pa1, pb);
        __syncthreads();
    }

    const int col = colBase + tx * 4;
    const float4 bia = *reinterpret_cast<const float4*>(bias + col);
#pragma unroll
    for (int i = 0; i < 8; i++) {
        int row = rowBase + ty * 8 + i;
        float4 v;
        v.x = fmaxf(acc[i][0] + bia.x, 0.f);
        v.y = fmaxf(acc[i][1] + bia.y, 0.f);
        v.z = fmaxf(acc[i][2] + bia.z, 0.f);
        v.w = fmaxf(acc[i][3] + bia.w, 0.f);
        *reinterpret_cast<float4*>(C + (size_t)row * NC + col) = v;
    }
}

// Launch 1: grid (9, 8, 2).
//   blockIdx.x < 8 : relu GEMMs (z = branch).  blockIdx.x == 8 : stats blocks.
__global__ void __launch_bounds__(256)
mi_relu(const float* __restrict__ hist, const float* __restrict__ path,
        const float* __restrict__ glob,
        const float* __restrict__ W1, const float* __restrict__ b1,
        const float* __restrict__ W1g, const float* __restrict__ b1g,
        float* __restrict__ hid1, float* __restrict__ hid2) {
    if (blockIdx.x == 8) {
        stats_block(path, glob);
        return;
    }
    __shared__ float As[2][16][132];
    __shared__ float Bs[2][16][64];
    if (blockIdx.z == 0)
        relu_body<256, false>(hist, nullptr, W1, b1, hid1, As, Bs);
    else
        relu_body<512, true>(hist, path, W1g, b1g, hid2, As, Bs);
}

// ---------------------------------------------------------------------------
// Launch 2: mu = A[1024,512] @ B[512,256] + bias, fused CLUB epilogue + final.
// 64x64 tile, 4x4 per thread, double-buffered, As padded to 68.
// Per element: 0.5*(E[y^2]_d - 2*mu*ybar_d + mu^2) - 0.5*(mu - y_id)^2
// Block partials -> double atomicAdd; last of 128 blocks writes out.
// ---------------------------------------------------------------------------
__global__ void __launch_bounds__(256)
mi_club(const float* __restrict__ hid1, const float* __restrict__ W2,
        const float* __restrict__ b2, const float* __restrict__ path,
        const float* __restrict__ hid2, const float* __restrict__ W2g,
        const float* __restrict__ b2g, const float* __restrict__ glob,
        float* __restrict__ out) {
    constexpr int K = 512, NC = 256, BM = 64, BN = 64, BK = 16, T = K / BK;
    __shared__ float As[2][BK][68];
    __shared__ float Bs[2][BK][64];

    const int z = blockIdx.z;
    const float* __restrict__ A = z ? hid2 : hid1;
    const float* __restrict__ B = z ? W2g : W2;
    const float* __restrict__ bias = z ? b2g : b2;
    const float* __restrict__ Y = z ? glob : path;

    const int tid = threadIdx.x;  // 256
    const int tx = tid & 15;      // 4 cols each
    const int ty = tid >> 4;      // 4 rows each
    const int rowBase = blockIdx.y * BM;
    const int colBase = blockIdx.x * BN;

    const int a_row = tid >> 2;       // 0..63
    const int a_kq = (tid & 3) * 4;   // 0,4,8,12
    const int b_k = tid >> 4;         // 0..15
    const int b_c = (tid & 15) * 4;   // 0..60

    auto ldA = [&](int t) {
        return *reinterpret_cast<const float4*>(
            A + (size_t)(rowBase + a_row) * K + t * BK + a_kq);
    };
    auto ldB = [&](int t) {
        return *reinterpret_cast<const float4*>(
            B + (size_t)(t * BK + b_k) * NC + colBase + b_c);
    };
    auto stTile = [&](int buf, float4 a4, float4 b4) {
        As[buf][a_kq + 0][a_row] = a4.x;
        As[buf][a_kq + 1][a_row] = a4.y;
        As[buf][a_kq + 2][a_row] = a4.z;
        As[buf][a_kq + 3][a_row] = a4.w;
        *reinterpret_cast<float4*>(&Bs[buf][b_k][b_c]) = b4;
    };

    float acc[4][4] = {};

    stTile(0, ldA(0), ldB(0));
    __syncthreads();

    for (int t = 0; t < T; t++) {
        int cur = t & 1;
        float4 pa, pb;
        if (t + 1 < T) { pa = ldA(t + 1); pb = ldB(t + 1); }
#pragma unroll
        for (int k = 0; k < BK; k++) {
            float4 av = *reinterpret_cast<const float4*>(&As[cur][k][ty * 4]);
            float4 bv = *reinterpret_cast<const float4*>(&Bs[cur][k][tx * 4]);
            float a[4] = {av.x, av.y, av.z, av.w};
            float b[4] = {bv.x, bv.y, bv.z, bv.w};
#pragma unroll
            for (int i = 0; i < 4; i++)
#pragma unroll
                for (int j = 0; j < 4; j++)
                    acc[i][j] = fmaf(a[i], b[j], acc[i][j]);
        }
        if (t + 1 < T) stTile((t + 1) & 1, pa, pb);
        __syncthreads();
    }

    // Fused CLUB epilogue
    const int col = colBase + tx * 4;
    const float4 bia = *reinterpret_cast<const float4*>(bias + col);
    const float4 sum4 = *reinterpret_cast<const float4*>(&g_colstats[z][0][col]);
    const float4 sq4 = *reinterpret_cast<const float4*>(&g_colstats[z][1][col]);
    const float ybar[4] = {sum4.x * (1.f / 1024.f), sum4.y * (1.f / 1024.f),
                           sum4.z * (1.f / 1024.f), sum4.w * (1.f / 1024.f)};
    const float ey2[4] = {sq4.x * (1.f / 1024.f), sq4.y * (1.f / 1024.f),
                          sq4.z * (1.f / 1024.f), sq4.w * (1.f / 1024.f)};
    const float bi[4] = {bia.x, bia.y, bia.z, bia.w};

    float local = 0.f;
#pragma unroll
    for (int i = 0; i < 4; i++) {
        int row = rowBase + ty * 4 + i;
        float4 y4 = *reinterpret_cast<const float4*>(Y + (size_t)row * 256 + col);
        float y[4] = {y4.x, y4.y, y4.z, y4.w};
#pragma unroll
        for (int j = 0; j < 4; j++) {
            float mu = acc[i][j] + bi[j];
            float d = mu - y[j];
            local += 0.5f * (ey2[j] - 2.f * mu * ybar[j] + mu * mu) - 0.5f * d * d;
        }
    }
    __shared__ float red[256];
    red[tid] = local;
    __syncthreads();
    for (int s = 128; s > 0; s >>= 1) {
        if (tid < s) red[tid] += red[tid + s];
        __syncthreads();
    }
    if (tid == 0) {
        atomicAdd(&g_acc, (double)red[0]);
        __threadfence();
        unsigned int done = atomicAdd(&g_cnt, 1u);
        if (done == 4 * 16 * 2 - 1) {  // last block: finalize
            double total = atomicAdd(&g_acc, 0.0);  // coherent read
            out[0] = (float)(total * (1.0 / 1024.0));
        }
    }
}

extern "C" void kernel_launch(void* const* d_in, const int* in_sizes, int n_in,
                              void* d_out, int out_size) {
    const float* hist = (const float*)d_in[0];
    const float* path = (const float*)d_in[1];
    const float* glob = (const float*)d_in[2];
    const float* W1 = (const float*)d_in[3];
    const float* b1 = (const float*)d_in[4];
    const float* W2 = (const float*)d_in[5];
    const float* b2 = (const float*)d_in[6];
    const float* W1g = (const float*)d_in[7];
    const float* b1g = (const float*)d_in[8];
    const float* W2g = (const float*)d_in[9];
    const float* b2g = (const float*)d_in[10];
    float* out = (float*)d_out;

    float *hid1 = nullptr, *hid2 = nullptr;
    cudaGetSymbolAddress((void**)&hid1, g_hid1);
    cudaGetSymbolAddress((void**)&hid2, g_hid2);

    mi_relu<<<dim3(9, 8, 2), 256>>>(hist, path, glob, W1, b1, W1g, b1g, hid1, hid2);
    mi_club<<<dim3(4, 16, 2), 256>>>(hid1, W2, b2, path, hid2, W2g, b2g, glob, out);
}